// round 15
// baseline (speedup 1.0000x reference)
#include <cuda_runtime.h>
#include <cuda_fp16.h>
#include <math.h>
#include <stdint.h>

#define TB 8
#define TS 4096
#define TD 512
#define TH 2048
#define TE 8
#define TP 16
#define NTOK (TB*TS)          /* 32768 tokens */

/* ---------------- device state ---------------- */
struct Acc { int counts[TE]; double psum[TE]; double zsum; };
__device__ Acc    g_acc;                /* zeroed by host memset each launch */
__device__ int    g_base[TE];
__device__ int    g_tok[TE * NTOK];     /* packed: token*2 + rank */
__device__ float  g_gate[TE * NTOK];
__device__ int    g_tmap[544];          /* (e<<16) | mtile */
__device__ int    g_ntiles;
__device__ __half g_H[(size_t)2 * NTOK * TH];     /* fp16 H scratch */
__device__ __half g_xh[(size_t)NTOK * TD];        /* fp16 x */
__device__ __half g_w1h[(size_t)TE * TH * TD];    /* W1^T: [e][h][d] (K-major) */
__device__ __half g_w3h[(size_t)TE * TH * TD];
__device__ __half g_w2h[(size_t)TE * TD * TH];    /* W2^T: [e][d][h] */

/* ---------------- helpers ---------------- */
__device__ __forceinline__ void mma_f16(
    float& c0, float& c1, float& c2, float& c3,
    unsigned a0, unsigned a1, unsigned a2, unsigned a3,
    unsigned b0, unsigned b1)
{
    asm volatile(
        "mma.sync.aligned.m16n8k16.row.col.f32.f16.f16.f32 "
        "{%0,%1,%2,%3}, {%4,%5,%6,%7}, {%8,%9}, {%0,%1,%2,%3};"
        : "+f"(c0), "+f"(c1), "+f"(c2), "+f"(c3)
        : "r"(a0), "r"(a1), "r"(a2), "r"(a3), "r"(b0), "r"(b1));
}

#define LDSM4(r0, r1, r2, r3, addr) \
    asm volatile("ldmatrix.sync.aligned.m8n8.x4.shared.b16 {%0,%1,%2,%3}, [%4];" \
                 : "=r"(r0), "=r"(r1), "=r"(r2), "=r"(r3) : "r"(addr))

#define CP16(dst, src) \
    asm volatile("cp.async.cg.shared.global [%0], [%1], 16;" :: "r"(dst), "l"(src))
#define CP_COMMIT() asm volatile("cp.async.commit_group;")
#define CP_WAIT1()  asm volatile("cp.async.wait_group 1;")
#define CP_WAIT0()  asm volatile("cp.async.wait_group 0;")

__device__ __forceinline__ unsigned sptr(const void* p) {
    return (unsigned)__cvta_generic_to_shared(p);
}

/* rows of 64 data halfs (128B) padded to 144B: conflict-free LDSM and STS phases */
#define ROWB 144

/* ffn1: 512 threads, CTA 128M x 128N x 2 gemms, 2-stage.
   Stage: A 128x144 (18432) @0, B1 128x144 @18432, B3 @36864 -> 55296 B/stage */
#define STG1   55296
#define HDR1   1024
#define FFN1_SMEM (HDR1 + 2 * STG1)     /* 111616 B -> 1 CTA/SM, 16 warps */
#define STG2   36864
#define HDR2   2048
#define FFN2_SMEM (HDR2 + 3 * STG2)     /* 112640 B -> 2 CTAs/SM */

/* ============ fused prep + router ============ */
__global__ __launch_bounds__(256) void prep_router_kernel(
    const float* __restrict__ x, const float* __restrict__ W1,
    const float* __restrict__ W2, const float* __restrict__ W3,
    const int* __restrict__ pid, const float* __restrict__ Wr,
    const float* __restrict__ Wp)
{
    const int z = blockIdx.z;
    const int tx = threadIdx.x, ty = threadIdx.y;
    const int tid = ty * 32 + tx;

    if (z == 0) {
        /* ---------------- router ---------------- */
        if (blockIdx.y >= 4) return;
        const int blk = blockIdx.y * 64 + blockIdx.x;   /* 0..255 */

        __shared__ float sWrT[TE * TD];
        __shared__ float sPsum[TE];
        __shared__ float sZsum;
        __shared__ int   sCnt[TE];
        __shared__ int   sGbase[TE];
        __shared__ unsigned char sE[256];
        __shared__ short sSlot[256];
        __shared__ float sG[256];

        for (int idx = tid; idx < TD * TE; idx += 256) {
            int d = idx >> 3, e = idx & 7;
            sWrT[e * TD + d] = Wr[idx];
        }
        if (tid < TE) { sPsum[tid] = 0.f; sCnt[tid] = 0; }
        if (tid == 0) sZsum = 0.f;
        __syncthreads();

        const int warp = tid >> 5, lane = tid & 31;
        const int tok0 = blk * 128 + warp * 16;

        float rpsum[TE];
        #pragma unroll
        for (int e = 0; e < TE; ++e) rpsum[e] = 0.f;
        float rzs = 0.f;

        for (int tt = 0; tt < 16; ++tt) {
            const int t = tok0 + tt;
            float acc[TE];
            #pragma unroll
            for (int e = 0; e < TE; ++e) acc[e] = 0.f;
            const float* xr = x + (size_t)t * TD;
            for (int i = lane; i < TD; i += 32) {
                float xv = xr[i];
                #pragma unroll
                for (int e = 0; e < TE; ++e)
                    acc[e] = fmaf(xv, sWrT[e * TD + i], acc[e]);
            }
            #pragma unroll
            for (int off = 16; off >= 1; off >>= 1) {
                #pragma unroll
                for (int e = 0; e < TE; ++e)
                    acc[e] += __shfl_down_sync(0xffffffffu, acc[e], off);
            }
            if (lane == 0) {
                const int b = t / TS;
                const int p = pid[b];
                float l[TE];
                float mx = -1e30f;
                #pragma unroll
                for (int e = 0; e < TE; ++e) {
                    l[e] = acc[e] + Wp[p * TE + e];
                    rzs += l[e] * l[e];
                    mx = fmaxf(mx, l[e]);
                }
                float s = 0.f, pr[TE];
                #pragma unroll
                for (int e = 0; e < TE; ++e) { pr[e] = expf(l[e] - mx); s += pr[e]; }
                const float inv = 1.f / s;
                #pragma unroll
                for (int e = 0; e < TE; ++e) rpsum[e] += pr[e] * inv;
                int i0 = 0;
                #pragma unroll
                for (int e = 1; e < TE; ++e) if (l[e] > l[i0]) i0 = e;
                int i1 = (i0 == 0) ? 1 : 0;
                #pragma unroll
                for (int e = 0; e < TE; ++e) if (e != i0 && l[e] > l[i1]) i1 = e;
                const float e1 = expf(l[i1] - l[i0]);
                const float g0 = 1.f / (1.f + e1);
                const float g1 = e1 * g0;
                const int s0 = atomicAdd(&sCnt[i0], 1);
                const int s1 = atomicAdd(&sCnt[i1], 1);
                const int loc = (warp * 16 + tt) * 2;
                sE[loc]     = (unsigned char)i0; sSlot[loc]     = (short)s0; sG[loc]     = g0;
                sE[loc + 1] = (unsigned char)i1; sSlot[loc + 1] = (short)s1; sG[loc + 1] = g1;
            }
        }
        if (lane == 0) {
            #pragma unroll
            for (int e = 0; e < TE; ++e) atomicAdd(&sPsum[e], rpsum[e]);
            atomicAdd(&sZsum, rzs);
        }
        __syncthreads();
        if (tid < TE) {
            sGbase[tid] = atomicAdd(&g_acc.counts[tid], sCnt[tid]);
            atomicAdd(&g_acc.psum[tid], (double)sPsum[tid]);
        }
        if (tid == 0) atomicAdd(&g_acc.zsum, (double)sZsum);
        __syncthreads();
        {
            const int e = sE[tid];
            const int pos = sGbase[e] + sSlot[tid];
            const int t = blk * 128 + (tid >> 1);
            g_tok[e * NTOK + pos]  = (t << 1) | (tid & 1);
            g_gate[e * NTOK + pos] = sG[tid];
        }
    } else if (z <= 24) {
        /* ---------------- weight transpose + fp16 round ---------------- */
        const int m = z - 1;
        const float* src; __half* dst; int R, C;
        if (m < 8)       { src = W1 + (size_t)m * TD * TH;        dst = g_w1h + (size_t)m * TH * TD;        R = TD; C = TH; }
        else if (m < 16) { src = W3 + (size_t)(m - 8) * TD * TH;  dst = g_w3h + (size_t)(m - 8) * TH * TD;  R = TD; C = TH; }
        else             { src = W2 + (size_t)(m - 16) * TH * TD; dst = g_w2h + (size_t)(m - 16) * TD * TH; R = TH; C = TD; }
        const int bx = blockIdx.x, by = blockIdx.y;
        if (bx * 32 >= C || by * 32 >= R) return;
        __shared__ float t[32][33];
        #pragma unroll
        for (int i = 0; i < 4; ++i)
            t[ty + 8 * i][tx] = src[(size_t)(by * 32 + ty + 8 * i) * C + bx * 32 + tx];
        __syncthreads();
        #pragma unroll
        for (int i = 0; i < 4; ++i)
            dst[(size_t)(bx * 32 + ty + 8 * i) * R + by * 32 + tx] = __float2half_rn(t[tx][ty + 8 * i]);
    } else {
        /* ---------------- x -> fp16 ---------------- */
        const size_t nb = (size_t)blockIdx.y * 64 + blockIdx.x;   /* 0..4095 */
        const size_t NX8 = (size_t)NTOK * TD / 8;
        const size_t stride = (size_t)4096 * 256;
        const float4* x4 = (const float4*)x;
        for (size_t i = nb * 256 + tid; i < NX8; i += stride) {
            float4 v0 = x4[2 * i], v1 = x4[2 * i + 1];
            __half2* dst = (__half2*)(g_xh + i * 8);
            dst[0] = __floats2half2_rn(v0.x, v0.y);
            dst[1] = __floats2half2_rn(v0.z, v0.w);
            dst[2] = __floats2half2_rn(v1.x, v1.y);
            dst[3] = __floats2half2_rn(v1.z, v1.w);
        }
    }
}

/* ---------------- prefix + tile map + losses ---------------- */
__global__ void prefix_losses_kernel(const float* __restrict__ Wp,
                                     float* __restrict__ out, int sbase)
{
    if (threadIdx.x != 0) return;
    int s = 0, idx = 0;
    for (int e = 0; e < TE; ++e) {
        g_base[e] = s;
        const int cnt = g_acc.counts[e];
        s += cnt;
        const int mt = (cnt + 127) >> 7;
        for (int m = 0; m < mt; ++m) g_tmap[idx++] = (e << 16) | m;
    }
    g_ntiles = idx;

    const double z = g_acc.zsum / (double)((size_t)NTOK * TE) * 0.001;
    double sb = 0.0;
    for (int e = 0; e < TE; ++e) {
        const double m = g_acc.psum[e] / (double)NTOK;
        const double d = m - 1.0 / TE;
        sb += d * d;
    }
    sb /= TE;
    float Pn[TP][TE];
    for (int p = 0; p < TP; ++p) {
        float mx = -1e30f;
        for (int e = 0; e < TE; ++e) mx = fmaxf(mx, Wp[p * TE + e]);
        float ss = 0.f;
        for (int e = 0; e < TE; ++e) { Pn[p][e] = expf(Wp[p * TE + e] - mx); ss += Pn[p][e]; }
        const float inv = 1.f / ss;
        for (int e = 0; e < TE; ++e) Pn[p][e] *= inv;
    }
    double acc = 0.0;
    for (int p = 0; p < TP; ++p)
        for (int q = 0; q < TP; ++q)
            if (p != q) {
                float d = 0.f;
                for (int e = 0; e < TE; ++e) d += Pn[p][e] * Pn[q][e];
                acc += (double)d;
            }
    const double spec = acc / (double)(TP * TP) * 0.1;
    out[sbase + 0] = (float)z;
    out[sbase + 1] = (float)sb;
    out[sbase + 2] = (float)spec;
}

/* ================= FFN stage 1 (fp16 mma + ldmatrix, BK=64, 2-stage, 512 threads) =================
   CTA 128M x 128N, both gemms. 16 warps = 4m x 4n; warp tile 32x32 per gemm.
   B tiles shared across 2x the M -> crossbar ratio 0.94, half the barriers per work.
   124 regs x 512 thr = full RF at 1 CTA/SM but still 16 warps/SM. */
__global__ __launch_bounds__(512, 1) void ffn1_kernel()
{
    if (blockIdx.x >= g_ntiles) return;
    const int mp  = g_tmap[blockIdx.x];
    const int e   = mp >> 16;
    const int m0  = (mp & 0xffff) << 7;
    const int cnt = g_acc.counts[e];
    const int n0   = blockIdx.y * 128;
    const int base = g_base[e];

    extern __shared__ char smc[];
    int* stok = (int*)smc;

    const int tid = threadIdx.x;
    if (tid < 128) {
        const int r = m0 + tid;
        stok[tid] = ((r < cnt) ? g_tok[e * NTOK + r] : g_tok[e * NTOK]) >> 1;
    }
    __syncthreads();

    const __half* W1e = g_w1h + (size_t)e * TH * TD;
    const __half* W3e = g_w3h + (size_t)e * TH * TD;

    const int warp = tid >> 5, lane = tid & 31;
    const int warp_m = warp & 3;     /* *32 */
    const int warp_n = warp >> 2;    /* 0..3 -> *32 */
    const int lg = lane >> 2, lt = lane & 3;

    const uint32_t a_off = (uint32_t)(warp_m * 32 + (lane & 15)) * ROWB + (lane >> 4) * 16;
    const uint32_t b_row = (uint32_t)(warp_n * 32 + (lane & 7) + ((lane >> 4) << 3));
    const uint32_t b_off = b_row * ROWB + ((lane >> 3) & 1) * 16;

    auto issue = [&](int it, int stg) {
        const int k0 = it * 64;
        char* S = smc + HDR1 + stg * STG1;
        /* 3072 chunks of 16B: A (1024), B1 (1024), B3 (1024); 512 thr x 6 */
        #pragma unroll
        for (int j = 0; j < 2; ++j) {
            const int q = tid + 512 * j;
            const int row = q >> 3, c = q & 7;
            CP16(sptr(S + row * ROWB + c * 16),
                 g_xh + (size_t)stok[row] * TD + k0 + c * 8);
        }
        #pragma unroll
        for (int j = 0; j < 2; ++j) {
            const int q = tid + 512 * j;
            const int row = q >> 3, c = q & 7;
            CP16(sptr(S + 18432 + row * ROWB + c * 16),
                 W1e + (size_t)(n0 + row) * TD + k0 + c * 8);
            CP16(sptr(S + 36864 + row * ROWB + c * 16),
                 W3e + (size_t)(n0 + row) * TD + k0 + c * 8);
        }
        CP_COMMIT();
    };

    float acc1[2][4][4], acc3[2][4][4];
    #pragma unroll
    for (int i = 0; i < 2; ++i)
        #pragma unroll
        for (int j = 0; j < 4; ++j)
            #pragma unroll
            for (int k = 0; k < 4; ++k) { acc1[i][j][k] = 0.f; acc3[i][j][k] = 0.f; }

    issue(0, 0);
    const int NIT = TD / 64;   /* 8 */

    #pragma unroll 1
    for (int it = 0; it < NIT; ++it) {
        CP_WAIT0();
        __syncthreads();
        if (it + 1 < NIT) issue(it + 1, (it + 1) & 1);

        const uint32_t Sb = sptr(smc + HDR1 + (it & 1) * STG1);
        const uint32_t Aa  = Sb + a_off;
        const uint32_t B1a = Sb + 18432 + b_off;
        const uint32_t B3a = Sb + 36864 + b_off;

        #pragma unroll
        for (int ks = 0; ks < 4; ++ks) {
            const uint32_t kb = ks * 32;
            unsigned a[2][4], b1f[4][2], b3f[4][2];
            LDSM4(a[0][0], a[0][1], a[0][2], a[0][3], Aa + kb);
            LDSM4(a[1][0], a[1][1], a[1][2], a[1][3], Aa + 16 * ROWB + kb);
            LDSM4(b1f[0][0], b1f[0][1], b1f[1][0], b1f[1][1], B1a + kb);
            LDSM4(b1f[2][0], b1f[2][1], b1f[3][0], b1f[3][1], B1a + 16 * ROWB + kb);
            LDSM4(b3f[0][0], b3f[0][1], b3f[1][0], b3f[1][1], B3a + kb);
            LDSM4(b3f[2][0], b3f[2][1], b3f[3][0], b3f[3][1], B3a + 16 * ROWB + kb);
            #pragma unroll
            for (int mi = 0; mi < 2; ++mi)
                #pragma unroll
                for (int ni = 0; ni < 4; ++ni) {
                    mma_f16(acc1[mi][ni][0], acc1[mi][ni][1], acc1[mi][ni][2], acc1[mi][ni][3],
                            a[mi][0], a[mi][1], a[mi][2], a[mi][3], b1f[ni][0], b1f[ni][1]);
                    mma_f16(acc3[mi][ni][0], acc3[mi][ni][1], acc3[mi][ni][2], acc3[mi][ni][3],
                            a[mi][0], a[mi][1], a[mi][2], a[mi][3], b3f[ni][0], b3f[ni][1]);
                }
        }
    }

    /* epilogue: h = (X@W1) * silu(X@W3), store fp16 */
    #pragma unroll
    for (int mi = 0; mi < 2; ++mi) {
        #pragma unroll
        for (int half = 0; half < 2; ++half) {
            const int rl = warp_m * 32 + mi * 16 + half * 8 + lg;
            const int r  = m0 + rl;
            if (r < cnt) {
                __half* hrow = g_H + (size_t)(base + r) * TH + n0 + warp_n * 32;
                #pragma unroll
                for (int ni = 0; ni < 4; ++ni) {
                    const float g1v = acc1[mi][ni][half * 2 + 0];
                    const float g1w = acc1[mi][ni][half * 2 + 1];
                    const float g3v = acc3[mi][ni][half * 2 + 0];
                    const float g3w = acc3[mi][ni][half * 2 + 1];
                    const float hx = g1v * (g3v / (1.f + expf(-g3v)));
                    const float hy = g1w * (g3w / (1.f + expf(-g3w)));
                    *(__half2*)(hrow + ni * 8 + 2 * lt) = __floats2half2_rn(hx, hy);
                }
            }
        }
    }
}

/* ================= FFN stage 2 (fp16 mma + ldmatrix, BK=64, 3-stage, atomic epilogue) =================
   Grid: x = n-tile (4), y = m-tile (520): 4 n-tiles co-resident per m-tile -> H L2 reuse. */
__global__ __launch_bounds__(256, 2) void ffn2_kernel(float* __restrict__ y)
{
    if (blockIdx.y >= g_ntiles) return;
    const int mp  = g_tmap[blockIdx.y];
    const int e   = mp >> 16;
    const int m0  = (mp & 0xffff) << 7;
    const int cnt = g_acc.counts[e];
    const int n0   = blockIdx.x * 128;
    const int base = g_base[e];

    extern __shared__ char smc[];
    int*   sslot = (int*)smc;            /* 128 */
    int*   stokT = (int*)(smc + 512);    /* 128 */
    float* sgate = (float*)(smc + 1024); /* 128 */

    const int tid = threadIdx.x;
    if (tid < 128) {
        const int r = m0 + tid;
        const int rc = (r < cnt) ? r : (cnt - 1);
        sslot[tid] = base + rc;
        stokT[tid] = g_tok[e * NTOK + rc] >> 1;
        sgate[tid] = (r < cnt) ? g_gate[e * NTOK + r] : 0.f;
    }
    __syncthreads();

    const __half* W2e = g_w2h + (size_t)e * TD * TH;

    const int warp = tid >> 5, lane = tid & 31;
    const int warp_m = warp >> 2;    /* *64 */
    const int warp_n = warp & 3;     /* *32 */
    const int lg = lane >> 2, lt = lane & 3;

    const uint32_t a_off = (uint32_t)(warp_m * 64 + (lane & 15)) * ROWB + (lane >> 4) * 16;
    const uint32_t b_row = (uint32_t)(warp_n * 32 + (lane & 7) + ((lane >> 4) << 3));
    const uint32_t b_off = b_row * ROWB + ((lane >> 3) & 1) * 16;

    auto issue = [&](int it, int stg) {
        const int k0 = it * 64;
        char* S = smc + HDR2 + stg * STG2;
        #pragma unroll
        for (int j = 0; j < 4; ++j) {
            const int q = tid + 256 * j;
            const int row = q >> 3, c = q & 7;
            CP16(sptr(S + row * ROWB + c * 16),
                 g_H + (size_t)sslot[row] * TH + k0 + c * 8);
        }
        #pragma unroll
        for (int j = 0; j < 4; ++j) {
            const int q = tid + 256 * j;
            const int row = q >> 3, c = q & 7;
            CP16(sptr(S + 18432 + row * ROWB + c * 16),
                 W2e + (size_t)(n0 + row) * TH + k0 + c * 8);
        }
        CP_COMMIT();
    };

    float acc[4][4][4];
    #pragma unroll
    for (int i = 0; i < 4; ++i)
        #pragma unroll
        for (int j = 0; j < 4; ++j)
            #pragma unroll
            for (int k = 0; k < 4; ++k) acc[i][j][k] = 0.f;

    issue(0, 0);
    issue(1, 1);
    int sa = 0, sc = 2;
    const int NIT = TH / 64;   /* 32 */

    #pragma unroll 1
    for (int it = 0; it < NIT; ++it) {
        if (it < NIT - 1) { CP_WAIT1(); } else { CP_WAIT0(); }
        __syncthreads();

        const uint32_t Sb = sptr(smc + HDR2 + sa * STG2);
        const uint32_t Aa = Sb + a_off;
        const uint32_t Ba = Sb + 18432 + b_off;

        #pragma unroll
        for (int ks = 0; ks < 4; ++ks) {
            const uint32_t kb = ks * 32;
            unsigned a[4][4], b[4][2];
            LDSM4(a[0][0], a[0][1], a[0][2], a[0][3], Aa + kb);
            LDSM4(a[1][0], a[1][1], a[1][2], a[1][3], Aa + 16 * ROWB + kb);
            LDSM4(a[2][0], a[2][1], a[2][2], a[2][3], Aa + 32 * ROWB + kb);
            LDSM4(a[3][0], a[3][1], a[3][2], a[3][3], Aa + 48 * ROWB + kb);
            LDSM4(b[0][0], b[0][1], b[1][0], b[1][1], Ba + kb);
            LDSM4(b[2][0], b[2][1], b[3][0], b[3][1], Ba + 16 * ROWB + kb);
            #pragma unroll
            for (int mi = 0; mi < 4; ++mi)
                #pragma unroll
                for (int ni = 0; ni < 4; ++ni)
                    mma_f16(acc[mi][ni][0], acc[mi][ni][1], acc[mi][ni][2], acc[mi][ni][3],
                            a[mi][0], a[mi][1], a[mi][2], a[mi][3], b[ni][0], b[ni][1]);
        }

        if (it + 2 < NIT) issue(it + 2, sc);
        if (++sa == 3) sa = 0;
        if (++sc == 3) sc = 0;
    }

    #pragma unroll
    for (int mi = 0; mi < 4; ++mi) {
        #pragma unroll
        for (int half = 0; half < 2; ++half) {
            const int rl = warp_m * 64 + mi * 16 + half * 8 + lg;
            if (m0 + rl < cnt) {
                const int t = stokT[rl];
                const float g = sgate[rl];
                float* yr = y + (size_t)t * TD + n0 + warp_n * 32;
                #pragma unroll
                for (int ni = 0; ni < 4; ++ni) {
                    const int col = ni * 8 + 2 * lt;
                    atomicAdd(&yr[col],     g * acc[mi][ni][half * 2 + 0]);
                    atomicAdd(&yr[col + 1], g * acc[mi][ni][half * 2 + 1]);
                }
            }
        }
    }
}

/* ---------------- launch ---------------- */
extern "C" void kernel_launch(void* const* d_in, const int* in_sizes, int n_in,
                              void* d_out, int out_size)
{
    const float* x  = (const float*)d_in[0];
    const int*   pid= (const int*)  d_in[1];
    const float* Wr = (const float*)d_in[2];
    const float* Wp = (const float*)d_in[3];
    const float* W1 = (const float*)d_in[4];
    const float* W2 = (const float*)d_in[5];
    const float* W3 = (const float*)d_in[6];
    float* out = (float*)d_out;

    static void* accAddr = nullptr;
    static int attr_done = 0;
    if (!attr_done) {
        cudaFuncSetAttribute(ffn1_kernel, cudaFuncAttributeMaxDynamicSharedMemorySize, FFN1_SMEM);
        cudaFuncSetAttribute(ffn2_kernel, cudaFuncAttributeMaxDynamicSharedMemorySize, FFN2_SMEM);
        cudaGetSymbolAddress(&accAddr, g_acc);
        attr_done = 1;
    }

    cudaMemsetAsync(d_out, 0, (size_t)out_size * sizeof(float));
    cudaMemsetAsync(accAddr, 0, sizeof(Acc));

    {
        dim3 gP(64, 64, 26), bP(32, 8);
        prep_router_kernel<<<gP, bP>>>(x, W1, W2, W3, pid, Wr, Wp);
    }
    prefix_losses_kernel<<<1, 1>>>(Wp, out, out_size - 3);

    dim3 gA(520, TH / 128, 1);
    ffn1_kernel<<<gA, 512, FFN1_SMEM>>>();

    dim3 gB(TD / 128, 520, 1);
    ffn2_kernel<<<gB, 256, FFN2_SMEM>>>(out);
}

// round 16
// speedup vs baseline: 1.1274x; 1.1274x over previous
#include <cuda_runtime.h>
#include <cuda_fp16.h>
#include <math.h>
#include <stdint.h>

#define TB 8
#define TS 4096
#define TD 512
#define TH 2048
#define TE 8
#define TP 16
#define NTOK (TB*TS)          /* 32768 tokens */

/* ---------------- device state ---------------- */
struct Acc { int counts[TE]; double psum[TE]; double zsum; };
__device__ Acc    g_acc;                /* zeroed by host memset each launch */
__device__ int    g_base[TE];
__device__ int    g_tok[TE * NTOK];     /* packed: token*2 + rank */
__device__ float  g_gate[TE * NTOK];
__device__ int    g_tmap[544];          /* (e<<16) | mtile */
__device__ int    g_ntiles;
__device__ __half g_H[(size_t)2 * NTOK * TH];     /* fp16 H scratch */
__device__ __half g_xh[(size_t)NTOK * TD];        /* fp16 x */
__device__ __half g_w1h[(size_t)TE * TH * TD];    /* W1^T: [e][h][d] (K-major) */
__device__ __half g_w3h[(size_t)TE * TH * TD];
__device__ __half g_w2h[(size_t)TE * TD * TH];    /* W2^T: [e][d][h] */

/* ---------------- helpers ---------------- */
__device__ __forceinline__ void mma_f16(
    float& c0, float& c1, float& c2, float& c3,
    unsigned a0, unsigned a1, unsigned a2, unsigned a3,
    unsigned b0, unsigned b1)
{
    asm volatile(
        "mma.sync.aligned.m16n8k16.row.col.f32.f16.f16.f32 "
        "{%0,%1,%2,%3}, {%4,%5,%6,%7}, {%8,%9}, {%0,%1,%2,%3};"
        : "+f"(c0), "+f"(c1), "+f"(c2), "+f"(c3)
        : "r"(a0), "r"(a1), "r"(a2), "r"(a3), "r"(b0), "r"(b1));
}

#define LDSM4(r0, r1, r2, r3, addr) \
    asm volatile("ldmatrix.sync.aligned.m8n8.x4.shared.b16 {%0,%1,%2,%3}, [%4];" \
                 : "=r"(r0), "=r"(r1), "=r"(r2), "=r"(r3) : "r"(addr))

#define CP16(dst, src) \
    asm volatile("cp.async.cg.shared.global [%0], [%1], 16;" :: "r"(dst), "l"(src))
#define CP_COMMIT() asm volatile("cp.async.commit_group;")
#define CP_WAIT1()  asm volatile("cp.async.wait_group 1;")
#define CP_WAIT0()  asm volatile("cp.async.wait_group 0;")

__device__ __forceinline__ unsigned sptr(const void* p) {
    return (unsigned)__cvta_generic_to_shared(p);
}

/* rows of 64 data halfs (128B) padded to 144B: conflict-free LDSM and STS phases */
#define ROWB 144

#define STG1   36864
#define HDR1   1024
#define FFN1_SMEM (HDR1 + 3 * STG1)     /* 111616 B -> 2 CTAs/SM */
#define STG2   36864
#define HDR2   2048
#define FFN2_SMEM (HDR2 + 3 * STG2)     /* 112640 B -> 2 CTAs/SM */

/* ============ fused prep + router + y-zero ============
   z=0    : router (256 blocks, by<4)
   z=1..24: weight transpose+cvt
   z=25   : x -> fp16
   z=26   : zero y (replaces serial cudaMemset of d_out) */
__global__ __launch_bounds__(256) void prep_router_kernel(
    const float* __restrict__ x, const float* __restrict__ W1,
    const float* __restrict__ W2, const float* __restrict__ W3,
    const int* __restrict__ pid, const float* __restrict__ Wr,
    const float* __restrict__ Wp, float* __restrict__ y, int ysize)
{
    const int z = blockIdx.z;
    const int tx = threadIdx.x, ty = threadIdx.y;
    const int tid = ty * 32 + tx;

    if (z == 0) {
        /* ---------------- router ---------------- */
        if (blockIdx.y >= 4) return;
        const int blk = blockIdx.y * 64 + blockIdx.x;   /* 0..255 */

        __shared__ float sWrT[TE * TD];
        __shared__ float sPsum[TE];
        __shared__ float sZsum;
        __shared__ int   sCnt[TE];
        __shared__ int   sGbase[TE];
        __shared__ unsigned char sE[256];
        __shared__ short sSlot[256];
        __shared__ float sG[256];

        for (int idx = tid; idx < TD * TE; idx += 256) {
            int d = idx >> 3, e = idx & 7;
            sWrT[e * TD + d] = Wr[idx];
        }
        if (tid < TE) { sPsum[tid] = 0.f; sCnt[tid] = 0; }
        if (tid == 0) sZsum = 0.f;
        __syncthreads();

        const int warp = tid >> 5, lane = tid & 31;
        const int tok0 = blk * 128 + warp * 16;

        float rpsum[TE];
        #pragma unroll
        for (int e = 0; e < TE; ++e) rpsum[e] = 0.f;
        float rzs = 0.f;

        for (int tt = 0; tt < 16; ++tt) {
            const int t = tok0 + tt;
            float acc[TE];
            #pragma unroll
            for (int e = 0; e < TE; ++e) acc[e] = 0.f;
            const float* xr = x + (size_t)t * TD;
            for (int i = lane; i < TD; i += 32) {
                float xv = xr[i];
                #pragma unroll
                for (int e = 0; e < TE; ++e)
                    acc[e] = fmaf(xv, sWrT[e * TD + i], acc[e]);
            }
            #pragma unroll
            for (int off = 16; off >= 1; off >>= 1) {
                #pragma unroll
                for (int e = 0; e < TE; ++e)
                    acc[e] += __shfl_down_sync(0xffffffffu, acc[e], off);
            }
            if (lane == 0) {
                const int b = t / TS;
                const int p = pid[b];
                float l[TE];
                float mx = -1e30f;
                #pragma unroll
                for (int e = 0; e < TE; ++e) {
                    l[e] = acc[e] + Wp[p * TE + e];
                    rzs += l[e] * l[e];
                    mx = fmaxf(mx, l[e]);
                }
                float s = 0.f, pr[TE];
                #pragma unroll
                for (int e = 0; e < TE; ++e) { pr[e] = expf(l[e] - mx); s += pr[e]; }
                const float inv = 1.f / s;
                #pragma unroll
                for (int e = 0; e < TE; ++e) rpsum[e] += pr[e] * inv;
                int i0 = 0;
                #pragma unroll
                for (int e = 1; e < TE; ++e) if (l[e] > l[i0]) i0 = e;
                int i1 = (i0 == 0) ? 1 : 0;
                #pragma unroll
                for (int e = 0; e < TE; ++e) if (e != i0 && l[e] > l[i1]) i1 = e;
                const float e1 = expf(l[i1] - l[i0]);
                const float g0 = 1.f / (1.f + e1);
                const float g1 = e1 * g0;
                const int s0 = atomicAdd(&sCnt[i0], 1);
                const int s1 = atomicAdd(&sCnt[i1], 1);
                const int loc = (warp * 16 + tt) * 2;
                sE[loc]     = (unsigned char)i0; sSlot[loc]     = (short)s0; sG[loc]     = g0;
                sE[loc + 1] = (unsigned char)i1; sSlot[loc + 1] = (short)s1; sG[loc + 1] = g1;
            }
        }
        if (lane == 0) {
            #pragma unroll
            for (int e = 0; e < TE; ++e) atomicAdd(&sPsum[e], rpsum[e]);
            atomicAdd(&sZsum, rzs);
        }
        __syncthreads();
        if (tid < TE) {
            sGbase[tid] = atomicAdd(&g_acc.counts[tid], sCnt[tid]);
            atomicAdd(&g_acc.psum[tid], (double)sPsum[tid]);
        }
        if (tid == 0) atomicAdd(&g_acc.zsum, (double)sZsum);
        __syncthreads();
        {
            const int e = sE[tid];
            const int pos = sGbase[e] + sSlot[tid];
            const int t = blk * 128 + (tid >> 1);
            g_tok[e * NTOK + pos]  = (t << 1) | (tid & 1);
            g_gate[e * NTOK + pos] = sG[tid];
        }
    } else if (z <= 24) {
        /* ---------------- weight transpose + fp16 round ---------------- */
        const int m = z - 1;
        const float* src; __half* dst; int R, C;
        if (m < 8)       { src = W1 + (size_t)m * TD * TH;        dst = g_w1h + (size_t)m * TH * TD;        R = TD; C = TH; }
        else if (m < 16) { src = W3 + (size_t)(m - 8) * TD * TH;  dst = g_w3h + (size_t)(m - 8) * TH * TD;  R = TD; C = TH; }
        else             { src = W2 + (size_t)(m - 16) * TH * TD; dst = g_w2h + (size_t)(m - 16) * TD * TH; R = TH; C = TD; }
        const int bx = blockIdx.x, by = blockIdx.y;
        if (bx * 32 >= C || by * 32 >= R) return;
        __shared__ float t[32][33];
        #pragma unroll
        for (int i = 0; i < 4; ++i)
            t[ty + 8 * i][tx] = src[(size_t)(by * 32 + ty + 8 * i) * C + bx * 32 + tx];
        __syncthreads();
        #pragma unroll
        for (int i = 0; i < 4; ++i)
            dst[(size_t)(bx * 32 + ty + 8 * i) * R + by * 32 + tx] = __float2half_rn(t[tx][ty + 8 * i]);
    } else if (z == 25) {
        /* ---------------- x -> fp16 ---------------- */
        const size_t nb = (size_t)blockIdx.y * 64 + blockIdx.x;   /* 0..4095 */
        const size_t NX8 = (size_t)NTOK * TD / 8;
        const size_t stride = (size_t)4096 * 256;
        const float4* x4 = (const float4*)x;
        for (size_t i = nb * 256 + tid; i < NX8; i += stride) {
            float4 v0 = x4[2 * i], v1 = x4[2 * i + 1];
            __half2* dst = (__half2*)(g_xh + i * 8);
            dst[0] = __floats2half2_rn(v0.x, v0.y);
            dst[1] = __floats2half2_rn(v0.z, v0.w);
            dst[2] = __floats2half2_rn(v1.x, v1.y);
            dst[3] = __floats2half2_rn(v1.z, v1.w);
        }
    } else {
        /* ---------------- zero y ---------------- */
        const size_t nb = (size_t)blockIdx.y * 64 + blockIdx.x;   /* 0..4095 */
        const size_t N4 = (size_t)ysize >> 2;
        const size_t stride = (size_t)4096 * 256;
        const float4 zv = make_float4(0.f, 0.f, 0.f, 0.f);
        float4* y4 = (float4*)y;
        for (size_t i = nb * 256 + tid; i < N4; i += stride)
            y4[i] = zv;
        if (nb == 0 && tid < 4) {
            const size_t tail = N4 * 4 + tid;
            if (tail < (size_t)ysize) y[tail] = 0.f;
        }
    }
}

/* ---------------- prefix + tile map + losses ---------------- */
__global__ void prefix_losses_kernel(const float* __restrict__ Wp,
                                     float* __restrict__ out, int sbase)
{
    if (threadIdx.x != 0) return;
    int s = 0, idx = 0;
    for (int e = 0; e < TE; ++e) {
        g_base[e] = s;
        const int cnt = g_acc.counts[e];
        s += cnt;
        const int mt = (cnt + 127) >> 7;
        for (int m = 0; m < mt; ++m) g_tmap[idx++] = (e << 16) | m;
    }
    g_ntiles = idx;

    const double z = g_acc.zsum / (double)((size_t)NTOK * TE) * 0.001;
    double sb = 0.0;
    for (int e = 0; e < TE; ++e) {
        const double m = g_acc.psum[e] / (double)NTOK;
        const double d = m - 1.0 / TE;
        sb += d * d;
    }
    sb /= TE;
    float Pn[TP][TE];
    for (int p = 0; p < TP; ++p) {
        float mx = -1e30f;
        for (int e = 0; e < TE; ++e) mx = fmaxf(mx, Wp[p * TE + e]);
        float ss = 0.f;
        for (int e = 0; e < TE; ++e) { Pn[p][e] = expf(Wp[p * TE + e] - mx); ss += Pn[p][e]; }
        const float inv = 1.f / ss;
        for (int e = 0; e < TE; ++e) Pn[p][e] *= inv;
    }
    double acc = 0.0;
    for (int p = 0; p < TP; ++p)
        for (int q = 0; q < TP; ++q)
            if (p != q) {
                float d = 0.f;
                for (int e = 0; e < TE; ++e) d += Pn[p][e] * Pn[q][e];
                acc += (double)d;
            }
    const double spec = acc / (double)(TP * TP) * 0.1;
    out[sbase + 0] = (float)z;
    out[sbase + 1] = (float)sb;
    out[sbase + 2] = (float)spec;
}

/* ================= FFN stage 1 (fp16 mma + ldmatrix, BK=64, 3-stage) ================= */
__global__ __launch_bounds__(256, 2) void ffn1_kernel()
{
    if (blockIdx.x >= g_ntiles) return;
    const int mp  = g_tmap[blockIdx.x];
    const int e   = mp >> 16;
    const int m0  = (mp & 0xffff) << 7;
    const int cnt = g_acc.counts[e];
    const int n0   = blockIdx.y * 64;
    const int base = g_base[e];

    extern __shared__ char smc[];
    int* stok = (int*)smc;

    const int tid = threadIdx.x;
    if (tid < 128) {
        const int r = m0 + tid;
        stok[tid] = ((r < cnt) ? g_tok[e * NTOK + r] : g_tok[e * NTOK]) >> 1;
    }
    __syncthreads();

    const __half* W1e = g_w1h + (size_t)e * TH * TD;
    const __half* W3e = g_w3h + (size_t)e * TH * TD;

    const int warp = tid >> 5, lane = tid & 31;
    const int warp_m = warp & 3;     /* *32 */
    const int warp_n = warp >> 2;    /* *32 */
    const int lg = lane >> 2, lt = lane & 3;

    const uint32_t a_off = (uint32_t)(warp_m * 32 + (lane & 15)) * ROWB + (lane >> 4) * 16;
    const uint32_t b_row = (uint32_t)(warp_n * 32 + (lane & 7) + ((lane >> 4) << 3));
    const uint32_t b_off = b_row * ROWB + ((lane >> 3) & 1) * 16;

    auto issue = [&](int it, int stg) {
        const int k0 = it * 64;
        char* S = smc + HDR1 + stg * STG1;
        #pragma unroll
        for (int j = 0; j < 4; ++j) {
            const int q = tid + 256 * j;
            const int row = q >> 3, c = q & 7;
            CP16(sptr(S + row * ROWB + c * 16),
                 g_xh + (size_t)stok[row] * TD + k0 + c * 8);
        }
        #pragma unroll
        for (int j = 0; j < 2; ++j) {
            const int q = tid + 256 * j;
            const int row = q >> 3, c = q & 7;
            CP16(sptr(S + 18432 + row * ROWB + c * 16),
                 W1e + (size_t)(n0 + row) * TD + k0 + c * 8);
            CP16(sptr(S + 27648 + row * ROWB + c * 16),
                 W3e + (size_t)(n0 + row) * TD + k0 + c * 8);
        }
        CP_COMMIT();
    };

    float acc1[2][4][4], acc3[2][4][4];
    #pragma unroll
    for (int i = 0; i < 2; ++i)
        #pragma unroll
        for (int j = 0; j < 4; ++j)
            #pragma unroll
            for (int k = 0; k < 4; ++k) { acc1[i][j][k] = 0.f; acc3[i][j][k] = 0.f; }

    issue(0, 0);
    issue(1, 1);
    int sa = 0, sc = 2;
    const int NIT = TD / 64;   /* 8 */

    #pragma unroll 1
    for (int it = 0; it < NIT; ++it) {
        if (it < NIT - 1) { CP_WAIT1(); } else { CP_WAIT0(); }
        __syncthreads();

        const uint32_t Sb = sptr(smc + HDR1 + sa * STG1);
        const uint32_t Aa  = Sb + a_off;
        const uint32_t B1a = Sb + 18432 + b_off;
        const uint32_t B3a = Sb + 27648 + b_off;

        #pragma unroll
        for (int ks = 0; ks < 4; ++ks) {
            const uint32_t kb = ks * 32;
            unsigned a[2][4], b1f[4][2], b3f[4][2];
            LDSM4(a[0][0], a[0][1], a[0][2], a[0][3], Aa + kb);
            LDSM4(a[1][0], a[1][1], a[1][2], a[1][3], Aa + 16 * ROWB + kb);
            LDSM4(b1f[0][0], b1f[0][1], b1f[1][0], b1f[1][1], B1a + kb);
            LDSM4(b1f[2][0], b1f[2][1], b1f[3][0], b1f[3][1], B1a + 16 * ROWB + kb);
            LDSM4(b3f[0][0], b3f[0][1], b3f[1][0], b3f[1][1], B3a + kb);
            LDSM4(b3f[2][0], b3f[2][1], b3f[3][0], b3f[3][1], B3a + 16 * ROWB + kb);
            #pragma unroll
            for (int mi = 0; mi < 2; ++mi)
                #pragma unroll
                for (int ni = 0; ni < 4; ++ni) {
                    mma_f16(acc1[mi][ni][0], acc1[mi][ni][1], acc1[mi][ni][2], acc1[mi][ni][3],
                            a[mi][0], a[mi][1], a[mi][2], a[mi][3], b1f[ni][0], b1f[ni][1]);
                    mma_f16(acc3[mi][ni][0], acc3[mi][ni][1], acc3[mi][ni][2], acc3[mi][ni][3],
                            a[mi][0], a[mi][1], a[mi][2], a[mi][3], b3f[ni][0], b3f[ni][1]);
                }
        }

        if (it + 2 < NIT) issue(it + 2, sc);
        if (++sa == 3) sa = 0;
        if (++sc == 3) sc = 0;
    }

    /* epilogue: h = (X@W1) * silu(X@W3), store fp16 */
    #pragma unroll
    for (int mi = 0; mi < 2; ++mi) {
        #pragma unroll
        for (int half = 0; half < 2; ++half) {
            const int rl = warp_m * 32 + mi * 16 + half * 8 + lg;
            const int r  = m0 + rl;
            if (r < cnt) {
                __half* hrow = g_H + (size_t)(base + r) * TH + n0 + warp_n * 32;
                #pragma unroll
                for (int ni = 0; ni < 4; ++ni) {
                    const float g1v = acc1[mi][ni][half * 2 + 0];
                    const float g1w = acc1[mi][ni][half * 2 + 1];
                    const float g3v = acc3[mi][ni][half * 2 + 0];
                    const float g3w = acc3[mi][ni][half * 2 + 1];
                    const float hx = g1v * (g3v / (1.f + expf(-g3v)));
                    const float hy = g1w * (g3w / (1.f + expf(-g3w)));
                    *(__half2*)(hrow + ni * 8 + 2 * lt) = __floats2half2_rn(hx, hy);
                }
            }
        }
    }
}

/* ================= FFN stage 2 (fp16 mma + ldmatrix, BK=64, 3-stage, atomic epilogue) =================
   Grid: x = n-tile (4), y = m-tile (520): 4 n-tiles co-resident per m-tile -> H L2 reuse. */
__global__ __launch_bounds__(256, 2) void ffn2_kernel(float* __restrict__ y)
{
    if (blockIdx.y >= g_ntiles) return;
    const int mp  = g_tmap[blockIdx.y];
    const int e   = mp >> 16;
    const int m0  = (mp & 0xffff) << 7;
    const int cnt = g_acc.counts[e];
    const int n0   = blockIdx.x * 128;
    const int base = g_base[e];

    extern __shared__ char smc[];
    int*   sslot = (int*)smc;            /* 128 */
    int*   stokT = (int*)(smc + 512);    /* 128 */
    float* sgate = (float*)(smc + 1024); /* 128 */

    const int tid = threadIdx.x;
    if (tid < 128) {
        const int r = m0 + tid;
        const int rc = (r < cnt) ? r : (cnt - 1);
        sslot[tid] = base + rc;
        stokT[tid] = g_tok[e * NTOK + rc] >> 1;
        sgate[tid] = (r < cnt) ? g_gate[e * NTOK + r] : 0.f;
    }
    __syncthreads();

    const __half* W2e = g_w2h + (size_t)e * TD * TH;

    const int warp = tid >> 5, lane = tid & 31;
    const int warp_m = warp >> 2;    /* *64 */
    const int warp_n = warp & 3;     /* *32 */
    const int lg = lane >> 2, lt = lane & 3;

    const uint32_t a_off = (uint32_t)(warp_m * 64 + (lane & 15)) * ROWB + (lane >> 4) * 16;
    const uint32_t b_row = (uint32_t)(warp_n * 32 + (lane & 7) + ((lane >> 4) << 3));
    const uint32_t b_off = b_row * ROWB + ((lane >> 3) & 1) * 16;

    auto issue = [&](int it, int stg) {
        const int k0 = it * 64;
        char* S = smc + HDR2 + stg * STG2;
        #pragma unroll
        for (int j = 0; j < 4; ++j) {
            const int q = tid + 256 * j;
            const int row = q >> 3, c = q & 7;
            CP16(sptr(S + row * ROWB + c * 16),
                 g_H + (size_t)sslot[row] * TH + k0 + c * 8);
        }
        #pragma unroll
        for (int j = 0; j < 4; ++j) {
            const int q = tid + 256 * j;
            const int row = q >> 3, c = q & 7;
            CP16(sptr(S + 18432 + row * ROWB + c * 16),
                 W2e + (size_t)(n0 + row) * TH + k0 + c * 8);
        }
        CP_COMMIT();
    };

    float acc[4][4][4];
    #pragma unroll
    for (int i = 0; i < 4; ++i)
        #pragma unroll
        for (int j = 0; j < 4; ++j)
            #pragma unroll
            for (int k = 0; k < 4; ++k) acc[i][j][k] = 0.f;

    issue(0, 0);
    issue(1, 1);
    int sa = 0, sc = 2;
    const int NIT = TH / 64;   /* 32 */

    #pragma unroll 1
    for (int it = 0; it < NIT; ++it) {
        if (it < NIT - 1) { CP_WAIT1(); } else { CP_WAIT0(); }
        __syncthreads();

        const uint32_t Sb = sptr(smc + HDR2 + sa * STG2);
        const uint32_t Aa = Sb + a_off;
        const uint32_t Ba = Sb + 18432 + b_off;

        #pragma unroll
        for (int ks = 0; ks < 4; ++ks) {
            const uint32_t kb = ks * 32;
            unsigned a[4][4], b[4][2];
            LDSM4(a[0][0], a[0][1], a[0][2], a[0][3], Aa + kb);
            LDSM4(a[1][0], a[1][1], a[1][2], a[1][3], Aa + 16 * ROWB + kb);
            LDSM4(a[2][0], a[2][1], a[2][2], a[2][3], Aa + 32 * ROWB + kb);
            LDSM4(a[3][0], a[3][1], a[3][2], a[3][3], Aa + 48 * ROWB + kb);
            LDSM4(b[0][0], b[0][1], b[1][0], b[1][1], Ba + kb);
            LDSM4(b[2][0], b[2][1], b[3][0], b[3][1], Ba + 16 * ROWB + kb);
            #pragma unroll
            for (int mi = 0; mi < 4; ++mi)
                #pragma unroll
                for (int ni = 0; ni < 4; ++ni)
                    mma_f16(acc[mi][ni][0], acc[mi][ni][1], acc[mi][ni][2], acc[mi][ni][3],
                            a[mi][0], a[mi][1], a[mi][2], a[mi][3], b[ni][0], b[ni][1]);
        }

        if (it + 2 < NIT) issue(it + 2, sc);
        if (++sa == 3) sa = 0;
        if (++sc == 3) sc = 0;
    }

    #pragma unroll
    for (int mi = 0; mi < 4; ++mi) {
        #pragma unroll
        for (int half = 0; half < 2; ++half) {
            const int rl = warp_m * 64 + mi * 16 + half * 8 + lg;
            if (m0 + rl < cnt) {
                const int t = stokT[rl];
                const float g = sgate[rl];
                float* yr = y + (size_t)t * TD + n0 + warp_n * 32;
                #pragma unroll
                for (int ni = 0; ni < 4; ++ni) {
                    const int col = ni * 8 + 2 * lt;
                    atomicAdd(&yr[col],     g * acc[mi][ni][half * 2 + 0]);
                    atomicAdd(&yr[col + 1], g * acc[mi][ni][half * 2 + 1]);
                }
            }
        }
    }
}

/* ---------------- launch ---------------- */
extern "C" void kernel_launch(void* const* d_in, const int* in_sizes, int n_in,
                              void* d_out, int out_size)
{
    const float* x  = (const float*)d_in[0];
    const int*   pid= (const int*)  d_in[1];
    const float* Wr = (const float*)d_in[2];
    const float* Wp = (const float*)d_in[3];
    const float* W1 = (const float*)d_in[4];
    const float* W2 = (const float*)d_in[5];
    const float* W3 = (const float*)d_in[6];
    float* out = (float*)d_out;

    static void* accAddr = nullptr;
    static int attr_done = 0;
    if (!attr_done) {
        cudaFuncSetAttribute(ffn1_kernel, cudaFuncAttributeMaxDynamicSharedMemorySize, FFN1_SMEM);
        cudaFuncSetAttribute(ffn2_kernel, cudaFuncAttributeMaxDynamicSharedMemorySize, FFN2_SMEM);
        cudaGetSymbolAddress(&accAddr, g_acc);
        attr_done = 1;
    }

    cudaMemsetAsync(accAddr, 0, sizeof(Acc));

    {
        dim3 gP(64, 64, 27), bP(32, 8);
        prep_router_kernel<<<gP, bP>>>(x, W1, W2, W3, pid, Wr, Wp, out, out_size);
    }
    prefix_losses_kernel<<<1, 1>>>(Wp, out, out_size - 3);

    dim3 gA(520, TH / 64, 1);
    ffn1_kernel<<<gA, 256, FFN1_SMEM>>>();

    dim3 gB(TD / 128, 520, 1);
    ffn2_kernel<<<gB, 256, FFN2_SMEM>>>(out);
}